// round 1
// baseline (speedup 1.0000x reference)
#include <cuda_runtime.h>

#define NN 10000
#define DD 256
#define H1 128
#define H2 64
#define NT ((NN + 127) >> 7)   // 79 tiles of 128

// ---- scratch (static device globals: allocation-free rule) ----
__device__ float g_dis[NN];          // degree, then rsqrt(degree)
__device__ float g_hw[NN * H1];      // x @ W1
__device__ float g_h[NN * H1];       // after agg + bias + relu
__device__ float g_hagg[NN * H1];    // A_norm @ h
__device__ float g_z[NN * H2];       // latent

// ---------------- degree / normalization ----------------
__global__ void k_deg_init() {
    int i = blockIdx.x * 256 + threadIdx.x;
    if (i < NN) g_dis[i] = 1.0f;                 // self-loop weight
}

__global__ void k_deg_acc(const int* __restrict__ col, const float* __restrict__ ew, int E) {
    int e = blockIdx.x * 256 + threadIdx.x;
    if (e < E) atomicAdd(&g_dis[col[e]], ew[e]);
}

__global__ void k_deg_fin() {
    int i = blockIdx.x * 256 + threadIdx.x;
    if (i < NN) g_dis[i] = rsqrtf(g_dis[i]);     // deg >= 1 always (self-loop)
}

// ---------------- GEMM1: g_hw = x @ W1  [N,256]x[256,128] ----------------
__global__ void __launch_bounds__(128) k_gemm1(const float* __restrict__ x,
                                               const float* __restrict__ W1) {
    __shared__ float xs[4 * DD];
    int r0 = blockIdx.x * 4;
    int t = threadIdx.x;
#pragma unroll
    for (int l = 0; l < 8; l++) {
        int idx = t + l * 128;
        int r = idx >> 8, k = idx & 255;
        xs[idx] = (r0 + r < NN) ? x[(size_t)(r0 + r) * DD + k] : 0.f;
    }
    __syncthreads();
    float a0 = 0, a1 = 0, a2 = 0, a3 = 0;
#pragma unroll 8
    for (int k = 0; k < DD; k++) {
        float w = W1[k * H1 + t];
        a0 += xs[k] * w;
        a1 += xs[DD + k] * w;
        a2 += xs[2 * DD + k] * w;
        a3 += xs[3 * DD + k] * w;
    }
    if (r0 + 0 < NN) g_hw[(r0 + 0) * H1 + t] = a0;
    if (r0 + 1 < NN) g_hw[(r0 + 1) * H1 + t] = a1;
    if (r0 + 2 < NN) g_hw[(r0 + 2) * H1 + t] = a2;
    if (r0 + 3 < NN) g_hw[(r0 + 3) * H1 + t] = a3;
}

// ---------------- aggregation: dst = A_norm @ src (128 features) ----------------
// P=0: src=g_hw dst=g_h ; P=1: src=g_h dst=g_hagg
template <int P>
__global__ void k_agg_init() {
    int idx = blockIdx.x * 256 + threadIdx.x;
    if (idx >= NN * H1) return;
    float d = g_dis[idx >> 7];
    if (P == 0) g_h[idx] = g_hw[idx] * d * d;      // self-loop term: dis_i * 1 * dis_i
    else        g_hagg[idx] = g_h[idx] * d * d;
}

template <int P>
__global__ void k_agg_edges(const int* __restrict__ row, const int* __restrict__ col,
                            const float* __restrict__ ew, int E) {
    int gid = blockIdx.x * 256 + threadIdx.x;
    int e = gid >> 5, lane = gid & 31;
    if (e >= E) return;
    int r = row[e], c = col[e];
    float w = g_dis[r] * ew[e] * g_dis[c];
    const float* src = (P == 0) ? g_hw : g_h;
    float* dst = (P == 0) ? g_h : g_hagg;
    float4 v = *(const float4*)&src[r * H1 + lane * 4];
    float* dp = &dst[c * H1 + lane * 4];
    atomicAdd(dp + 0, v.x * w);
    atomicAdd(dp + 1, v.y * w);
    atomicAdd(dp + 2, v.z * w);
    atomicAdd(dp + 3, v.w * w);
}

__global__ void k_relu_bias(const float* __restrict__ b1) {
    int idx = blockIdx.x * 256 + threadIdx.x;
    if (idx >= NN * H1) return;
    float v = g_h[idx] + b1[idx & (H1 - 1)];
    g_h[idx] = fmaxf(v, 0.f);
}

// ---------------- z = (hagg@W2+b2) + noise * exp(hagg@W3+b3) ----------------
__global__ void k_z(const float* __restrict__ W2, const float* __restrict__ b2,
                    const float* __restrict__ W3, const float* __restrict__ b3,
                    const float* __restrict__ noise) {
    int idx = blockIdx.x * 256 + threadIdx.x;
    if (idx >= NN * H2) return;
    int i = idx >> 6, c = idx & 63;
    const float* hr = &g_hagg[i * H1];
    float m = 0.f, s = 0.f;
#pragma unroll 8
    for (int k = 0; k < H1; k++) {
        float h = hr[k];                 // broadcast within warp (same row)
        m += h * W2[k * H2 + c];
        s += h * W3[k * H2 + c];
    }
    m += b2[c];
    s += b3[c];
    g_z[idx] = m + noise[idx] * expf(s);
}

// ---------------- decode: out = sigmoid(z @ z^T), symmetric (upper tiles + mirror) ----------------
__global__ void __launch_bounds__(256) k_decode(float* __restrict__ out) {
    int bi = blockIdx.y, bj = blockIdx.x;
    if (bj < bi) return;                           // symmetry: only upper tiles
    extern __shared__ float sm[];
    float* zi = sm;                                // [64][128], k-major (transposed)
    float* zj = sm + 64 * 128;
    int t = threadIdx.x;
    int rowBase = bi << 7, colBase = bj << 7;

    // load + transpose both 128x64 z tiles into smem (zero-pad OOB rows)
#pragma unroll
    for (int l = 0; l < 8; l++) {
        int idx = t + (l << 8);                    // float4 index 0..2047
        int r = idx >> 4;                          // 0..127
        int k0 = (idx & 15) << 2;                  // 0..60 step 4
        float4 v = make_float4(0, 0, 0, 0), u = make_float4(0, 0, 0, 0);
        if (rowBase + r < NN) v = *(const float4*)&g_z[(rowBase + r) * H2 + k0];
        if (colBase + r < NN) u = *(const float4*)&g_z[(colBase + r) * H2 + k0];
        zi[(k0 + 0) * 128 + r] = v.x; zi[(k0 + 1) * 128 + r] = v.y;
        zi[(k0 + 2) * 128 + r] = v.z; zi[(k0 + 3) * 128 + r] = v.w;
        zj[(k0 + 0) * 128 + r] = u.x; zj[(k0 + 1) * 128 + r] = u.y;
        zj[(k0 + 2) * 128 + r] = u.z; zj[(k0 + 3) * 128 + r] = u.w;
    }
    __syncthreads();

    int tx = t & 15, ty = t >> 4;
    float acc[8][8];
#pragma unroll
    for (int i = 0; i < 8; i++)
#pragma unroll
        for (int j = 0; j < 8; j++) acc[i][j] = 0.f;

    // split-tile mapping: rows {ty*4..+3, 64+ty*4..+3}, cols {tx*4..+3, 64+tx*4..+3}
#pragma unroll 4
    for (int k = 0; k < H2; k++) {
        const float* ak = zi + k * 128;
        const float* bk = zj + k * 128;
        float4 A0 = *(const float4*)&ak[ty * 4];
        float4 A1 = *(const float4*)&ak[64 + ty * 4];
        float4 B0 = *(const float4*)&bk[tx * 4];
        float4 B1 = *(const float4*)&bk[64 + tx * 4];
        float a[8] = {A0.x, A0.y, A0.z, A0.w, A1.x, A1.y, A1.z, A1.w};
        float b[8] = {B0.x, B0.y, B0.z, B0.w, B1.x, B1.y, B1.z, B1.w};
#pragma unroll
        for (int i = 0; i < 8; i++)
#pragma unroll
            for (int j = 0; j < 8; j++) acc[i][j] += a[i] * b[j];
    }

    // sigmoid in place
#pragma unroll
    for (int i = 0; i < 8; i++)
#pragma unroll
        for (int j = 0; j < 8; j++)
            acc[i][j] = 1.0f / (1.0f + __expf(-acc[i][j]));

    // own tile (coalesced float4 rows)
#pragma unroll
    for (int i = 0; i < 8; i++) {
        int r = rowBase + ((i < 4) ? (ty * 4 + i) : (64 + ty * 4 + i - 4));
        if (r >= NN) continue;
        size_t base = (size_t)r * NN;
        int c0 = colBase + tx * 4;
        int c1 = colBase + 64 + tx * 4;
        if (c0 < NN)
            *(float4*)&out[base + c0] = make_float4(acc[i][0], acc[i][1], acc[i][2], acc[i][3]);
        if (c1 < NN)
            *(float4*)&out[base + c1] = make_float4(acc[i][4], acc[i][5], acc[i][6], acc[i][7]);
    }

    // mirror tile (transpose write; each float4 covers one 32B-aligned sector half)
    if (bj > bi) {
#pragma unroll
        for (int j = 0; j < 8; j++) {
            int c = colBase + ((j < 4) ? (tx * 4 + j) : (64 + tx * 4 + j - 4));
            if (c >= NN) continue;
            size_t base = (size_t)c * NN;
            int r0 = rowBase + ty * 4;
            int r1 = rowBase + 64 + ty * 4;
            if (r0 < NN)
                *(float4*)&out[base + r0] = make_float4(acc[0][j], acc[1][j], acc[2][j], acc[3][j]);
            if (r1 < NN)
                *(float4*)&out[base + r1] = make_float4(acc[4][j], acc[5][j], acc[6][j], acc[7][j]);
        }
    }
}

extern "C" void kernel_launch(void* const* d_in, const int* in_sizes, int n_in,
                              void* d_out, int out_size) {
    const float* x     = (const float*)d_in[0];
    const int*   ei    = (const int*)d_in[1];     // [2, E] int32
    const float* ew    = (const float*)d_in[2];
    const float* noise = (const float*)d_in[3];
    const float* W1    = (const float*)d_in[4];
    const float* b1    = (const float*)d_in[5];
    const float* W2    = (const float*)d_in[6];
    const float* b2    = (const float*)d_in[7];
    const float* W3    = (const float*)d_in[8];
    const float* b3    = (const float*)d_in[9];
    float* out = (float*)d_out;

    int E = in_sizes[2];
    const int* row = ei;
    const int* col = ei + E;

    k_deg_init<<<(NN + 255) / 256, 256>>>();
    k_deg_acc<<<(E + 255) / 256, 256>>>(col, ew, E);
    k_deg_fin<<<(NN + 255) / 256, 256>>>();

    k_gemm1<<<(NN + 3) / 4, 128>>>(x, W1);

    k_agg_init<0><<<(NN * H1 + 255) / 256, 256>>>();
    k_agg_edges<0><<<(E * 32 + 255) / 256, 256>>>(row, col, ew, E);
    k_relu_bias<<<(NN * H1 + 255) / 256, 256>>>(b1);

    k_agg_init<1><<<(NN * H1 + 255) / 256, 256>>>();
    k_agg_edges<1><<<(E * 32 + 255) / 256, 256>>>(row, col, ew, E);

    k_z<<<(NN * H2 + 255) / 256, 256>>>(W2, b2, W3, b3, noise);

    cudaFuncSetAttribute(k_decode, cudaFuncAttributeMaxDynamicSharedMemorySize, 65536);
    k_decode<<<dim3(NT, NT), 256, 65536>>>(out);
}

// round 4
// speedup vs baseline: 1.4925x; 1.4925x over previous
#include <cuda_runtime.h>
#include <cstdint>

#define NN 10000
#define DD 256
#define H1 128
#define H2 64
#define NT ((NN + 127) >> 7)   // 79 tiles of 128
#define ZST 68                 // smem stride for z tiles (conflict-free frag loads)
#define TST 130                // smem stride for transpose re-stage

// ---- scratch (static device globals: allocation-free rule) ----
__device__ float g_dis[NN];          // degree, then rsqrt(degree)
__device__ float g_hw[NN * H1];      // x @ W1
__device__ float g_h[NN * H1];       // after agg + bias + relu
__device__ float g_hagg[NN * H1];    // A_norm @ h
__device__ float g_z[NN * H2];       // latent (tf32-rounded)

// ---------------- degree / normalization ----------------
__global__ void k_deg_init() {
    int i = blockIdx.x * 256 + threadIdx.x;
    if (i < NN) g_dis[i] = 1.0f;                 // self-loop weight
}

__global__ void k_deg_acc(const int* __restrict__ col, const float* __restrict__ ew, int E) {
    int e = blockIdx.x * 256 + threadIdx.x;
    if (e < E) atomicAdd(&g_dis[col[e]], ew[e]);
}

__global__ void k_deg_fin() {
    int i = blockIdx.x * 256 + threadIdx.x;
    if (i < NN) g_dis[i] = rsqrtf(g_dis[i]);     // deg >= 1 always (self-loop)
}

// ---------------- GEMM1: g_hw = x @ W1  [N,256]x[256,128], smem-staged ----------------
__global__ void __launch_bounds__(256) k_gemm1(const float* __restrict__ x,
                                               const float* __restrict__ W1) {
    __shared__ float xs[32][33];
    __shared__ float ws[32][128];
    int t = threadIdx.x;
    int r0 = blockIdx.x * 32;
    int tx = t & 31, ty = t >> 5;
    float acc[4][4];
#pragma unroll
    for (int i = 0; i < 4; i++)
#pragma unroll
        for (int j = 0; j < 4; j++) acc[i][j] = 0.f;

    for (int kc = 0; kc < DD; kc += 32) {
        {   // x tile: 32 rows x 32 k
            int r = t >> 3;
            int k0 = (t & 7) * 4;
            float4 v = make_float4(0, 0, 0, 0);
            if (r0 + r < NN) v = *(const float4*)&x[(size_t)(r0 + r) * DD + kc + k0];
            xs[r][k0] = v.x; xs[r][k0 + 1] = v.y; xs[r][k0 + 2] = v.z; xs[r][k0 + 3] = v.w;
        }
#pragma unroll
        for (int l = 0; l < 4; l++) {   // W tile: 32 k x 128 cols
            int idx = t + l * 256;
            int k = idx >> 5;
            int c4 = (idx & 31) * 4;
            *(float4*)&ws[k][c4] = *(const float4*)&W1[(size_t)(kc + k) * H1 + c4];
        }
        __syncthreads();
#pragma unroll
        for (int kk = 0; kk < 32; kk++) {
            float a0 = xs[ty * 4 + 0][kk], a1 = xs[ty * 4 + 1][kk];
            float a2 = xs[ty * 4 + 2][kk], a3 = xs[ty * 4 + 3][kk];
            float4 bv = *(float4*)&ws[kk][tx * 4];
            acc[0][0] += a0 * bv.x; acc[0][1] += a0 * bv.y; acc[0][2] += a0 * bv.z; acc[0][3] += a0 * bv.w;
            acc[1][0] += a1 * bv.x; acc[1][1] += a1 * bv.y; acc[1][2] += a1 * bv.z; acc[1][3] += a1 * bv.w;
            acc[2][0] += a2 * bv.x; acc[2][1] += a2 * bv.y; acc[2][2] += a2 * bv.z; acc[2][3] += a2 * bv.w;
            acc[3][0] += a3 * bv.x; acc[3][1] += a3 * bv.y; acc[3][2] += a3 * bv.z; acc[3][3] += a3 * bv.w;
        }
        __syncthreads();
    }
#pragma unroll
    for (int i = 0; i < 4; i++) {
        int r = r0 + ty * 4 + i;
        if (r < NN)
            *(float4*)&g_hw[(size_t)r * H1 + tx * 4] =
                make_float4(acc[i][0], acc[i][1], acc[i][2], acc[i][3]);
    }
}

// ---------------- aggregation: dst = A_norm @ src (128 features) ----------------
template <int P>
__global__ void k_agg_init() {
    int idx = blockIdx.x * 256 + threadIdx.x;
    if (idx >= NN * H1) return;
    float d = g_dis[idx >> 7];
    if (P == 0) g_h[idx] = g_hw[idx] * d * d;
    else        g_hagg[idx] = g_h[idx] * d * d;
}

template <int P>
__global__ void k_agg_edges(const int* __restrict__ row, const int* __restrict__ col,
                            const float* __restrict__ ew, int E) {
    int gid = blockIdx.x * 256 + threadIdx.x;
    int e = gid >> 5, lane = gid & 31;
    if (e >= E) return;
    int r = row[e], c = col[e];
    float w = g_dis[r] * ew[e] * g_dis[c];
    const float* src = (P == 0) ? g_hw : g_h;
    float* dst = (P == 0) ? g_h : g_hagg;
    float4 v = *(const float4*)&src[r * H1 + lane * 4];
    float* dp = &dst[c * H1 + lane * 4];
    atomicAdd(dp + 0, v.x * w);
    atomicAdd(dp + 1, v.y * w);
    atomicAdd(dp + 2, v.z * w);
    atomicAdd(dp + 3, v.w * w);
}

__global__ void k_relu_bias(const float* __restrict__ b1) {
    int idx = blockIdx.x * 256 + threadIdx.x;
    if (idx >= NN * H1) return;
    float v = g_h[idx] + b1[idx & (H1 - 1)];
    g_h[idx] = fmaxf(v, 0.f);
}

// ---------------- z = (hagg@W2+b2) + noise * exp(hagg@W3+b3), tf32-rounded ----------------
__global__ void __launch_bounds__(256) k_z(const float* __restrict__ W2, const float* __restrict__ b2,
                                           const float* __restrict__ W3, const float* __restrict__ b3,
                                           const float* __restrict__ noise) {
    extern __shared__ float dyn[];
    float* ws2 = dyn;               // [H1*H2]
    float* ws3 = dyn + H1 * H2;     // [H1*H2]
    float* bs  = dyn + 2 * H1 * H2; // [2*H2]
    int t = threadIdx.x;
    for (int i = t; i < H1 * H2; i += 256) { ws2[i] = W2[i]; ws3[i] = W3[i]; }
    if (t < H2) { bs[t] = b2[t]; bs[H2 + t] = b3[t]; }
    __syncthreads();
    int c = t & 63, slot = t >> 6;
    for (int i = blockIdx.x * 4 + slot; i < NN; i += gridDim.x * 4) {
        const float* hr = &g_hagg[(size_t)i * H1];
        float m = 0.f, s = 0.f;
#pragma unroll 8
        for (int k = 0; k < H1; k++) {
            float h = hr[k];
            m += h * ws2[k * H2 + c];
            s += h * ws3[k * H2 + c];
        }
        float zv = m + bs[c] + noise[(size_t)i * H2 + c] * expf(s + bs[H2 + c]);
        uint32_t u;
        asm("cvt.rna.tf32.f32 %0, %1;" : "=r"(u) : "f"(zv));
        g_z[(size_t)i * H2 + c] = __uint_as_float(u);
    }
}

// ---------------- decode: out = sigmoid(z @ z^T), tf32 HMMA, symmetric ----------------
__global__ void __launch_bounds__(256) k_decode(float* __restrict__ out) {
    int bi = blockIdx.y, bj = blockIdx.x;
    if (bj < bi) return;
    extern __shared__ float sm[];
    float* zi = sm;                  // [128][ZST] row-major (r, k)
    float* zj = sm + 128 * ZST;
    int t = threadIdx.x;
    int lane = t & 31, w = t >> 5;
    int rowBase = bi << 7, colBase = bj << 7;

    // load both 128x64 z tiles (zero-pad OOB rows)
#pragma unroll
    for (int l = 0; l < 8; l++) {
        int idx = t + (l << 8);
        int r = idx >> 4;
        int k0 = (idx & 15) << 2;
        float4 v = make_float4(0, 0, 0, 0), u = make_float4(0, 0, 0, 0);
        if (rowBase + r < NN) v = *(const float4*)&g_z[(size_t)(rowBase + r) * H2 + k0];
        if (colBase + r < NN) u = *(const float4*)&g_z[(size_t)(colBase + r) * H2 + k0];
        *(float4*)&zi[r * ZST + k0] = v;
        *(float4*)&zj[r * ZST + k0] = u;
    }
    __syncthreads();

    int wy = w >> 2, wx = w & 3;     // warp tile: rows wy*64..+63, cols wx*32..+31
    int g = lane >> 2, q = lane & 3;

    float acc[4][4][4];
#pragma unroll
    for (int mt = 0; mt < 4; mt++)
#pragma unroll
        for (int nt = 0; nt < 4; nt++)
#pragma unroll
            for (int i = 0; i < 4; i++) acc[mt][nt][i] = 0.f;

#pragma unroll
    for (int ks = 0; ks < 8; ks++) {
        int k0 = ks * 8 + q;
        uint32_t a[4][4], b[4][2];
#pragma unroll
        for (int mt = 0; mt < 4; mt++) {
            int r = wy * 64 + mt * 16 + g;
            a[mt][0] = __float_as_uint(zi[r * ZST + k0]);
            a[mt][1] = __float_as_uint(zi[(r + 8) * ZST + k0]);
            a[mt][2] = __float_as_uint(zi[r * ZST + k0 + 4]);
            a[mt][3] = __float_as_uint(zi[(r + 8) * ZST + k0 + 4]);
        }
#pragma unroll
        for (int nt = 0; nt < 4; nt++) {
            int c = wx * 32 + nt * 8 + g;
            b[nt][0] = __float_as_uint(zj[c * ZST + k0]);
            b[nt][1] = __float_as_uint(zj[c * ZST + k0 + 4]);
        }
#pragma unroll
        for (int mt = 0; mt < 4; mt++)
#pragma unroll
            for (int nt = 0; nt < 4; nt++)
                asm volatile(
                    "mma.sync.aligned.m16n8k8.row.col.f32.tf32.tf32.f32 "
                    "{%0,%1,%2,%3}, {%4,%5,%6,%7}, {%8,%9}, {%0,%1,%2,%3};\n"
                    : "+f"(acc[mt][nt][0]), "+f"(acc[mt][nt][1]),
                      "+f"(acc[mt][nt][2]), "+f"(acc[mt][nt][3])
                    : "r"(a[mt][0]), "r"(a[mt][1]), "r"(a[mt][2]), "r"(a[mt][3]),
                      "r"(b[nt][0]), "r"(b[nt][1]));
    }

    // sigmoid in place
#pragma unroll
    for (int mt = 0; mt < 4; mt++)
#pragma unroll
        for (int nt = 0; nt < 4; nt++)
#pragma unroll
            for (int i = 0; i < 4; i++)
                acc[mt][nt][i] = 1.0f / (1.0f + __expf(-acc[mt][nt][i]));

    // own tile: float2 coalesced writes (c0 even, NN even -> c0+1 in range iff c0 is)
#pragma unroll
    for (int mt = 0; mt < 4; mt++)
#pragma unroll
        for (int nt = 0; nt < 4; nt++) {
            int r0 = rowBase + wy * 64 + mt * 16 + g;
            int c0 = colBase + wx * 32 + nt * 8 + q * 2;
            if (c0 < NN) {
                if (r0 < NN)
                    *(float2*)&out[(size_t)r0 * NN + c0] =
                        make_float2(acc[mt][nt][0], acc[mt][nt][1]);
                if (r0 + 8 < NN)
                    *(float2*)&out[(size_t)(r0 + 8) * NN + c0] =
                        make_float2(acc[mt][nt][2], acc[mt][nt][3]);
            }
        }

    // mirror tile via smem transpose re-stage (coalesced column writes)
    if (bj > bi) {
        __syncthreads();            // all zi/zj reads done before overwrite
        float* st = sm;             // [128][TST]
#pragma unroll
        for (int mt = 0; mt < 4; mt++)
#pragma unroll
            for (int nt = 0; nt < 4; nt++) {
                int lr = wy * 64 + mt * 16 + g;
                int lc = wx * 32 + nt * 8 + q * 2;
                *(float2*)&st[lr * TST + lc] = make_float2(acc[mt][nt][0], acc[mt][nt][1]);
                *(float2*)&st[(lr + 8) * TST + lc] = make_float2(acc[mt][nt][2], acc[mt][nt][3]);
            }
        __syncthreads();
#pragma unroll 4
        for (int it = 0; it < 64; it++) {
            int task = w * 64 + it;
            int c = task >> 2;
            int r = (task & 3) * 32 + lane;
            int gc = colBase + c, gr = rowBase + r;
            if (gc < NN && gr < NN)
                out[(size_t)gc * NN + gr] = st[r * TST + c];
        }
    }
}

extern "C" void kernel_launch(void* const* d_in, const int* in_sizes, int n_in,
                              void* d_out, int out_size) {
    const float* x     = (const float*)d_in[0];
    const int*   ei    = (const int*)d_in[1];     // [2, E] int32
    const float* ew    = (const float*)d_in[2];
    const float* noise = (const float*)d_in[3];
    const float* W1    = (const float*)d_in[4];
    const float* b1    = (const float*)d_in[5];
    const float* W2    = (const float*)d_in[6];
    const float* b2    = (const float*)d_in[7];
    const float* W3    = (const float*)d_in[8];
    const float* b3    = (const float*)d_in[9];
    float* out = (float*)d_out;

    int E = in_sizes[2];
    const int* row = ei;
    const int* col = ei + E;

    // host-side, idempotent, graph-capture-safe (not stream ops)
    cudaFuncSetAttribute(k_z, cudaFuncAttributeMaxDynamicSharedMemorySize, 66048);
    cudaFuncSetAttribute(k_decode, cudaFuncAttributeMaxDynamicSharedMemorySize, 69632);

    k_deg_init<<<(NN + 255) / 256, 256>>>();
    k_deg_acc<<<(E + 255) / 256, 256>>>(col, ew, E);
    k_deg_fin<<<(NN + 255) / 256, 256>>>();

    k_gemm1<<<(NN + 31) / 32, 256>>>(x, W1);

    k_agg_init<0><<<(NN * H1 + 255) / 256, 256>>>();
    k_agg_edges<0><<<(E * 32 + 255) / 256, 256>>>(row, col, ew, E);
    k_relu_bias<<<(NN * H1 + 255) / 256, 256>>>(b1);

    k_agg_init<1><<<(NN * H1 + 255) / 256, 256>>>();
    k_agg_edges<1><<<(E * 32 + 255) / 256, 256>>>(row, col, ew, E);

    k_z<<<250, 256, 66048>>>(W2, b2, W3, b3, noise);

    k_decode<<<dim3(NT, NT), 256, 69632>>>(out);
}

// round 6
// speedup vs baseline: 1.7899x; 1.1992x over previous
#include <cuda_runtime.h>
#include <cstdint>

#define NN 10000
#define DD 256
#define H1 128
#define H2 64
#define NT ((NN + 127) >> 7)   // 79 decode tiles of 128
#define ZST 68                 // decode z-tile smem stride
#define TST 130                // decode transpose re-stage stride
#define AST 36                 // gemm1 A smem stride (k-chunk 32 + pad) -> banks 4g+q distinct
#define WST 136                // gemm1 W smem stride (136 % 32 == 8 -> b-frag conflict-free)

// ---- scratch (static device globals: allocation-free rule) ----
__device__ float g_dis[NN];          // degree, then rsqrt(degree)
__device__ float g_hw[NN * H1];      // x @ W1
__device__ float g_h[NN * H1];       // after agg + bias + relu
__device__ float g_hagg[NN * H1];    // A_norm @ h
__device__ float g_z[NN * H2];       // latent (tf32-rounded)

__device__ __forceinline__ uint32_t f2tf32(float f) {
    uint32_t u;
    asm("cvt.rna.tf32.f32 %0, %1;" : "=r"(u) : "f"(f));
    return u;
}

// ---------------- degree / normalization ----------------
__global__ void k_deg_init() {
    int i = blockIdx.x * 256 + threadIdx.x;
    if (i < NN) g_dis[i] = 1.0f;                 // self-loop weight
}

__global__ void k_deg_acc(const int* __restrict__ col, const float* __restrict__ ew, int E) {
    int e = blockIdx.x * 256 + threadIdx.x;
    if (e < E) atomicAdd(&g_dis[col[e]], ew[e]);
}

__global__ void k_deg_fin() {
    int i = blockIdx.x * 256 + threadIdx.x;
    if (i < NN) g_dis[i] = rsqrtf(g_dis[i]);     // deg >= 1 always (self-loop)
}

// ---------------- GEMM1: g_hw = x @ W1  [N,256]x[256,128], tf32 HMMA ----------------
// Block: 256 thr, 64 rows x 128 cols. Warp (wy in 0..1, wx in 0..3): 32 rows x 32 cols.
__global__ void __launch_bounds__(256) k_gemm1(const float* __restrict__ x,
                                               const float* __restrict__ W1) {
    __shared__ float as_[64 * AST];      // A chunk [r][k], tf32 bits
    __shared__ float ws[32 * WST];       // W chunk [k][n], tf32 bits
    int t = threadIdx.x;
    int lane = t & 31, w = t >> 5;
    int rowBase = blockIdx.x << 6;
    int wy = w >> 2, wx = w & 3;
    int g = lane >> 2, q = lane & 3;

    float acc[2][4][4];
#pragma unroll
    for (int mt = 0; mt < 2; mt++)
#pragma unroll
        for (int nt = 0; nt < 4; nt++)
#pragma unroll
            for (int i = 0; i < 4; i++) acc[mt][nt][i] = 0.f;

    for (int kc = 0; kc < DD; kc += 32) {
        // A chunk: 64 rows x 32 k = 512 float4; 2 per thread
#pragma unroll
        for (int l = 0; l < 2; l++) {
            int idx = t + (l << 8);
            int r = idx >> 3;
            int k0 = (idx & 7) << 2;
            float4 v = make_float4(0, 0, 0, 0);
            if (rowBase + r < NN) v = *(const float4*)&x[(size_t)(rowBase + r) * DD + kc + k0];
            float* d = &as_[r * AST + k0];
            d[0] = __uint_as_float(f2tf32(v.x));
            d[1] = __uint_as_float(f2tf32(v.y));
            d[2] = __uint_as_float(f2tf32(v.z));
            d[3] = __uint_as_float(f2tf32(v.w));
        }
        // W chunk: 32 k x 128 n = 1024 float4; 4 per thread
#pragma unroll
        for (int l = 0; l < 4; l++) {
            int idx = t + (l << 8);
            int k = idx >> 5;
            int n0 = (idx & 31) << 2;
            float4 v = *(const float4*)&W1[(size_t)(kc + k) * H1 + n0];
            float* d = &ws[k * WST + n0];
            d[0] = __uint_as_float(f2tf32(v.x));
            d[1] = __uint_as_float(f2tf32(v.y));
            d[2] = __uint_as_float(f2tf32(v.z));
            d[3] = __uint_as_float(f2tf32(v.w));
        }
        __syncthreads();
#pragma unroll
        for (int ks = 0; ks < 4; ks++) {
            int k0 = ks * 8 + q;
            uint32_t a[2][4], b[4][2];
#pragma unroll
            for (int mt = 0; mt < 2; mt++) {
                int r = wy * 32 + mt * 16 + g;
                a[mt][0] = __float_as_uint(as_[r * AST + k0]);
                a[mt][1] = __float_as_uint(as_[(r + 8) * AST + k0]);
                a[mt][2] = __float_as_uint(as_[r * AST + k0 + 4]);
                a[mt][3] = __float_as_uint(as_[(r + 8) * AST + k0 + 4]);
            }
#pragma unroll
            for (int nt = 0; nt < 4; nt++) {
                int n = wx * 32 + nt * 8 + g;
                b[nt][0] = __float_as_uint(ws[k0 * WST + n]);
                b[nt][1] = __float_as_uint(ws[(k0 + 4) * WST + n]);
            }
#pragma unroll
            for (int mt = 0; mt < 2; mt++)
#pragma unroll
                for (int nt = 0; nt < 4; nt++)
                    asm volatile(
                        "mma.sync.aligned.m16n8k8.row.col.f32.tf32.tf32.f32 "
                        "{%0,%1,%2,%3}, {%4,%5,%6,%7}, {%8,%9}, {%0,%1,%2,%3};\n"
                        : "+f"(acc[mt][nt][0]), "+f"(acc[mt][nt][1]),
                          "+f"(acc[mt][nt][2]), "+f"(acc[mt][nt][3])
                        : "r"(a[mt][0]), "r"(a[mt][1]), "r"(a[mt][2]), "r"(a[mt][3]),
                          "r"(b[nt][0]), "r"(b[nt][1]));
        }
        __syncthreads();
    }
    // epilogue: float2 writes
#pragma unroll
    for (int mt = 0; mt < 2; mt++)
#pragma unroll
        for (int nt = 0; nt < 4; nt++) {
            int r0 = rowBase + wy * 32 + mt * 16 + g;
            int c0 = wx * 32 + nt * 8 + q * 2;
            if (r0 < NN)
                *(float2*)&g_hw[(size_t)r0 * H1 + c0] =
                    make_float2(acc[mt][nt][0], acc[mt][nt][1]);
            if (r0 + 8 < NN)
                *(float2*)&g_hw[(size_t)(r0 + 8) * H1 + c0] =
                    make_float2(acc[mt][nt][2], acc[mt][nt][3]);
        }
}

// ---------------- aggregation: dst = A_norm @ src (128 features) ----------------
template <int P>
__global__ void k_agg_init() {
    int idx = blockIdx.x * 256 + threadIdx.x;
    if (idx >= NN * H1) return;
    float d = g_dis[idx >> 7];
    if (P == 0) g_h[idx] = g_hw[idx] * d * d;
    else        g_hagg[idx] = g_h[idx] * d * d;
}

template <int P>
__global__ void k_agg_edges(const int* __restrict__ row, const int* __restrict__ col,
                            const float* __restrict__ ew, int E) {
    int gid = blockIdx.x * 256 + threadIdx.x;
    int e = gid >> 5, lane = gid & 31;
    if (e >= E) return;
    int r = row[e], c = col[e];
    float w = g_dis[r] * ew[e] * g_dis[c];
    const float* src = (P == 0) ? g_hw : g_h;
    float* dst = (P == 0) ? g_h : g_hagg;
    float4 v = *(const float4*)&src[r * H1 + lane * 4];
    float* dp = &dst[c * H1 + lane * 4];
    asm volatile("red.global.add.v4.f32 [%0], {%1,%2,%3,%4};"
                 :: "l"(dp), "f"(v.x * w), "f"(v.y * w), "f"(v.z * w), "f"(v.w * w)
                 : "memory");
}

__global__ void k_relu_bias(const float* __restrict__ b1) {
    int idx = blockIdx.x * 256 + threadIdx.x;
    if (idx >= NN * H1) return;
    float v = g_h[idx] + b1[idx & (H1 - 1)];
    g_h[idx] = fmaxf(v, 0.f);
}

// ---------------- z = (hagg@W2+b2) + noise * exp(hagg@W3+b3), tf32-rounded ----------------
__global__ void __launch_bounds__(256) k_z(const float* __restrict__ W2, const float* __restrict__ b2,
                                           const float* __restrict__ W3, const float* __restrict__ b3,
                                           const float* __restrict__ noise) {
    extern __shared__ float dyn[];
    float* ws2 = dyn;               // [H1*H2]
    float* ws3 = dyn + H1 * H2;     // [H1*H2]
    float* bs  = dyn + 2 * H1 * H2; // [2*H2]
    int t = threadIdx.x;
    for (int i = t; i < H1 * H2; i += 256) { ws2[i] = W2[i]; ws3[i] = W3[i]; }
    if (t < H2) { bs[t] = b2[t]; bs[H2 + t] = b3[t]; }
    __syncthreads();
    int c = t & 63, slot = t >> 6;
    for (int i = blockIdx.x * 4 + slot; i < NN; i += gridDim.x * 4) {
        const float* hr = &g_hagg[(size_t)i * H1];
        float m = 0.f, s = 0.f;
#pragma unroll 8
        for (int k = 0; k < H1; k++) {
            float h = hr[k];
            m += h * ws2[k * H2 + c];
            s += h * ws3[k * H2 + c];
        }
        float zv = m + bs[c] + noise[(size_t)i * H2 + c] * expf(s + bs[H2 + c]);
        g_z[(size_t)i * H2 + c] = __uint_as_float(f2tf32(zv));
    }
}

// ---------------- decode: out = sigmoid(z @ z^T), tf32 HMMA, symmetric ----------------
__global__ void __launch_bounds__(256) k_decode(float* __restrict__ out) {
    int bi = blockIdx.y, bj = blockIdx.x;
    if (bj < bi) return;
    extern __shared__ float sm[];
    float* zi = sm;                  // [128][ZST] row-major (r, k)
    float* zj = sm + 128 * ZST;
    int t = threadIdx.x;
    int lane = t & 31, w = t >> 5;
    int rowBase = bi << 7, colBase = bj << 7;

#pragma unroll
    for (int l = 0; l < 8; l++) {
        int idx = t + (l << 8);
        int r = idx >> 4;
        int k0 = (idx & 15) << 2;
        float4 v = make_float4(0, 0, 0, 0), u = make_float4(0, 0, 0, 0);
        if (rowBase + r < NN) v = *(const float4*)&g_z[(size_t)(rowBase + r) * H2 + k0];
        if (colBase + r < NN) u = *(const float4*)&g_z[(size_t)(colBase + r) * H2 + k0];
        *(float4*)&zi[r * ZST + k0] = v;
        *(float4*)&zj[r * ZST + k0] = u;
    }
    __syncthreads();

    int wy = w >> 2, wx = w & 3;
    int g = lane >> 2, q = lane & 3;

    float acc[4][4][4];
#pragma unroll
    for (int mt = 0; mt < 4; mt++)
#pragma unroll
        for (int nt = 0; nt < 4; nt++)
#pragma unroll
            for (int i = 0; i < 4; i++) acc[mt][nt][i] = 0.f;

#pragma unroll
    for (int ks = 0; ks < 8; ks++) {
        int k0 = ks * 8 + q;
        uint32_t a[4][4], b[4][2];
#pragma unroll
        for (int mt = 0; mt < 4; mt++) {
            int r = wy * 64 + mt * 16 + g;
            a[mt][0] = __float_as_uint(zi[r * ZST + k0]);
            a[mt][1] = __float_as_uint(zi[(r + 8) * ZST + k0]);
            a[mt][2] = __float_as_uint(zi[r * ZST + k0 + 4]);
            a[mt][3] = __float_as_uint(zi[(r + 8) * ZST + k0 + 4]);
        }
#pragma unroll
        for (int nt = 0; nt < 4; nt++) {
            int c = wx * 32 + nt * 8 + g;
            b[nt][0] = __float_as_uint(zj[c * ZST + k0]);
            b[nt][1] = __float_as_uint(zj[c * ZST + k0 + 4]);
        }
#pragma unroll
        for (int mt = 0; mt < 4; mt++)
#pragma unroll
            for (int nt = 0; nt < 4; nt++)
                asm volatile(
                    "mma.sync.aligned.m16n8k8.row.col.f32.tf32.tf32.f32 "
                    "{%0,%1,%2,%3}, {%4,%5,%6,%7}, {%8,%9}, {%0,%1,%2,%3};\n"
                    : "+f"(acc[mt][nt][0]), "+f"(acc[mt][nt][1]),
                      "+f"(acc[mt][nt][2]), "+f"(acc[mt][nt][3])
                    : "r"(a[mt][0]), "r"(a[mt][1]), "r"(a[mt][2]), "r"(a[mt][3]),
                      "r"(b[nt][0]), "r"(b[nt][1]));
    }

#pragma unroll
    for (int mt = 0; mt < 4; mt++)
#pragma unroll
        for (int nt = 0; nt < 4; nt++)
#pragma unroll
            for (int i = 0; i < 4; i++)
                acc[mt][nt][i] = 1.0f / (1.0f + __expf(-acc[mt][nt][i]));

#pragma unroll
    for (int mt = 0; mt < 4; mt++)
#pragma unroll
        for (int nt = 0; nt < 4; nt++) {
            int r0 = rowBase + wy * 64 + mt * 16 + g;
            int c0 = colBase + wx * 32 + nt * 8 + q * 2;
            if (c0 < NN) {
                if (r0 < NN)
                    *(float2*)&out[(size_t)r0 * NN + c0] =
                        make_float2(acc[mt][nt][0], acc[mt][nt][1]);
                if (r0 + 8 < NN)
                    *(float2*)&out[(size_t)(r0 + 8) * NN + c0] =
                        make_float2(acc[mt][nt][2], acc[mt][nt][3]);
            }
        }

    if (bj > bi) {
        __syncthreads();
        float* st = sm;              // [128][TST]
#pragma unroll
        for (int mt = 0; mt < 4; mt++)
#pragma unroll
            for (int nt = 0; nt < 4; nt++) {
                int lr = wy * 64 + mt * 16 + g;
                int lc = wx * 32 + nt * 8 + q * 2;
                *(float2*)&st[lr * TST + lc] = make_float2(acc[mt][nt][0], acc[mt][nt][1]);
                *(float2*)&st[(lr + 8) * TST + lc] = make_float2(acc[mt][nt][2], acc[mt][nt][3]);
            }
        __syncthreads();
#pragma unroll 4
        for (int it = 0; it < 64; it++) {
            int task = w * 64 + it;
            int c = task >> 2;
            int r = (task & 3) * 32 + lane;
            int gc = colBase + c, gr = rowBase + r;
            if (gc < NN && gr < NN)
                out[(size_t)gc * NN + gr] = st[r * TST + c];
        }
    }
}

extern "C" void kernel_launch(void* const* d_in, const int* in_sizes, int n_in,
                              void* d_out, int out_size) {
    const float* x     = (const float*)d_in[0];
    const int*   ei    = (const int*)d_in[1];     // [2, E] int32
    const float* ew    = (const float*)d_in[2];
    const float* noise = (const float*)d_in[3];
    const float* W1    = (const float*)d_in[4];
    const float* b1    = (const float*)d_in[5];
    const float* W2    = (const float*)d_in[6];
    const float* b2    = (const float*)d_in[7];
    const float* W3    = (const float*)d_in[8];
    const float* b3    = (const float*)d_in[9];
    float* out = (float*)d_out;

    int E = in_sizes[2];
    const int* row = ei;
    const int* col = ei + E;

    cudaFuncSetAttribute(k_z, cudaFuncAttributeMaxDynamicSharedMemorySize, 66048);
    cudaFuncSetAttribute(k_decode, cudaFuncAttributeMaxDynamicSharedMemorySize, 69632);

    k_deg_init<<<(NN + 255) / 256, 256>>>();
    k_deg_acc<<<(E + 255) / 256, 256>>>(col, ew, E);
    k_deg_fin<<<(NN + 255) / 256, 256>>>();

    k_gemm1<<<(NN + 63) / 64, 256>>>(x, W1);

    k_agg_init<0><<<(NN * H1 + 255) / 256, 256>>>();
    k_agg_edges<0><<<(E * 32 + 255) / 256, 256>>>(row, col, ew, E);
    k_relu_bias<<<(NN * H1 + 255) / 256, 256>>>(b1);

    k_agg_init<1><<<(NN * H1 + 255) / 256, 256>>>();
    k_agg_edges<1><<<(E * 32 + 255) / 256, 256>>>(row, col, ew, E);

    k_z<<<250, 256, 66048>>>(W2, b2, W3, b3, noise);

    k_decode<<<dim3(NT, NT), 256, 69632>>>(out);
}